// round 9
// baseline (speedup 1.0000x reference)
#include <cuda_runtime.h>
#include <cstdint>

#define B_    64
#define S_    4096
#define F_    64
#define G4_   256   // 4 * F_

// ---------------- scratch (no cudaMalloc allowed) ----------------
__device__ float g_bufA[(size_t)B_ * S_ * F_];    // conv0 out / conv2 out
__device__ float g_bufB[(size_t)B_ * S_ * F_];    // conv1 out
__device__ float g_xw0[(size_t)B_ * S_ * G4_];    // layer0 gate pre-activations
__device__ float g_xw1[(size_t)B_ * S_ * G4_];    // layer1 gate pre-activations
__device__ int   g_prog[B_];                      // producer progress flags
__device__ float g_cfinal[B_ * F_];

typedef unsigned long long ull;

// ---------------- packed f32x2 helpers (sm_103a FFMA2 path) ----------------
__device__ __forceinline__ ull fma2(ull a, ull b, ull c) {
    ull d;
    asm("fma.rn.f32x2 %0, %1, %2, %3;" : "=l"(d) : "l"(a), "l"(b), "l"(c));
    return d;
}
__device__ __forceinline__ ull add2(ull a, ull b) {
    ull d;
    asm("add.rn.f32x2 %0, %1, %2;" : "=l"(d) : "l"(a), "l"(b));
    return d;
}
__device__ __forceinline__ ull dup2(float a) {
    ull d;
    asm("mov.b64 %0, {%1, %1};" : "=l"(d) : "f"(a));
    return d;
}
__device__ __forceinline__ ull pk2(float lo, float hi) {
    ull d;
    asm("mov.b64 %0, {%1, %2};" : "=l"(d) : "f"(lo), "f"(hi));
    return d;
}
__device__ __forceinline__ float2 upk2(ull v) {
    float2 r;
    asm("mov.b64 {%0, %1}, %2;" : "=f"(r.x), "=f"(r.y) : "l"(v));
    return r;
}

// HW tanh.approx (single MUFU)
__device__ __forceinline__ float tanh_fast(float x) {
    float r;
    asm("tanh.approx.f32 %0, %1;" : "=f"(r) : "f"(x));
    return r;
}
__device__ __forceinline__ float sig_fast(float x) {
    return fmaf(0.5f, tanh_fast(0.5f * x), 0.5f);
}

// ---------------------------------------------------------------------------
// Fused conv1d / GEMM kernel (unchanged, known-good R2/R6 version).
// ---------------------------------------------------------------------------
template <int KW, bool RELU>
__global__ void __launch_bounds__(256)
conv_gemm(const float* __restrict__ xin, const float* __restrict__ w,
          const float* __restrict__ bias, float* __restrict__ out,
          int Cin, int Cout) {
    constexpr int PAD = KW / 2;
    constexpr int RX = 64 + KW - 1;

    __shared__ __align__(16) float xs[66][16];
    __shared__ __align__(16) float ws[KW][16][64];

    const int tid = threadIdx.x;
    const int tx = tid & 15;
    const int ty = tid >> 4;
    const int s0 = blockIdx.x * 64;
    const int co0 = blockIdx.y * 64;
    const int b = blockIdx.z;

    const float* xb = xin + (size_t)b * S_ * Cin;

    ull a01[4], a23[4];
#pragma unroll
    for (int i = 0; i < 4; i++) { a01[i] = 0ull; a23[i] = 0ull; }

    for (int ck = 0; ck < Cin; ck += 16) {
        __syncthreads();
        for (int idx = tid; idx < RX * 16; idx += 256) {
            int r = idx >> 4, k = idx & 15;
            int sg = s0 + r - PAD;
            float v = 0.0f;
            if (sg >= 0 && sg < S_) v = xb[(size_t)sg * Cin + ck + k];
            xs[r][k] = v;
        }
        for (int idx = tid; idx < KW * 16 * 64; idx += 256) {
            int c = idx & 63, k = (idx >> 6) & 15, dk = idx >> 10;
            ws[dk][k][c] = w[((size_t)dk * Cin + (ck + k)) * Cout + co0 + c];
        }
        __syncthreads();

#pragma unroll
        for (int dk = 0; dk < KW; dk++) {
#pragma unroll
            for (int k = 0; k < 16; k++) {
                ulonglong2 wv =
                    *reinterpret_cast<const ulonglong2*>(&ws[dk][k][tx << 2]);
#pragma unroll
                for (int i = 0; i < 4; i++) {
                    ull av = dup2(xs[ty * 4 + i + dk][k]);
                    a01[i] = fma2(av, wv.x, a01[i]);
                    a23[i] = fma2(av, wv.y, a23[i]);
                }
            }
        }
    }

    const int c0 = co0 + (tx << 2);
    const float bb0 = bias[c0 + 0], bb1 = bias[c0 + 1];
    const float bb2 = bias[c0 + 2], bb3 = bias[c0 + 3];
#pragma unroll
    for (int i = 0; i < 4; i++) {
        float2 v01 = upk2(a01[i]);
        float2 v23 = upk2(a23[i]);
        float4 o;
        o.x = v01.x + bb0; o.y = v01.y + bb1;
        o.z = v23.x + bb2; o.w = v23.y + bb3;
        if (RELU) {
            o.x = fmaxf(o.x, 0.0f); o.y = fmaxf(o.y, 0.0f);
            o.z = fmaxf(o.z, 0.0f); o.w = fmaxf(o.w, 0.0f);
        }
        int sg = s0 + ty * 4 + i;
        *reinterpret_cast<float4*>(&out[((size_t)b * S_ + sg) * Cout + c0]) = o;
    }
}

// ---------------------------------------------------------------------------
// Pipelined 2-layer LSTM recurrence, TWO independent batch chains per CTA.
// Blocks 0..31: producers, batches (2p, 2p+1), layer 0. Fused Wh0/Wx1 dots
// per chain (R6 scheme), publish xw1 for both, flag on prog[2p].
// Blocks 32..63: consumers, same batch pair, layer 1.
// Chain A's dependency tail overlaps chain B's issue; barriers amortized 2x.
// Weight columns are register-resident and SHARED between the two chains.
// ---------------------------------------------------------------------------
__global__ void __launch_bounds__(256, 1)
lstm_pipe(const float* __restrict__ xw0, const float* __restrict__ Wh0,
          const float* __restrict__ Wx1, const float* __restrict__ b1v,
          const float* __restrict__ Wh1,
          float* __restrict__ xw1, int* __restrict__ prog,
          float* __restrict__ c_final) {
    const int p = blockIdx.x & 31;
    const bool producer = blockIdx.x < 32;
    const int bA = 2 * p, bB = 2 * p + 1;
    const int g = threadIdx.x;
    const int gtype = g >> 6;

    __shared__ __align__(16) float hA_s[F_], hB_s[F_];
    __shared__ float gbufA[G4_], gbufB[G4_];

    const ulonglong2* h4A = reinterpret_cast<const ulonglong2*>(hA_s);
    const ulonglong2* h4B = reinterpret_cast<const ulonglong2*>(hB_s);

    if (producer) {
        ull wA[32], wB[32];
#pragma unroll
        for (int k2 = 0; k2 < 32; k2++) {
            wA[k2] = pk2(Wh0[(size_t)(2 * k2) * G4_ + g],
                         Wh0[(size_t)(2 * k2 + 1) * G4_ + g]);
            wB[k2] = pk2(Wx1[(size_t)(2 * k2) * G4_ + g],
                         Wx1[(size_t)(2 * k2 + 1) * G4_ + g]);
        }
        const float b1g = b1v[g];

        if (g < F_) { hA_s[g] = 0.0f; hB_s[g] = 0.0f; }
        float cA = 0.0f, cB = 0.0f;

        const float* xwbA = xw0 + (size_t)bA * S_ * G4_ + g;
        const float* xwbB = xw0 + (size_t)bB * S_ * G4_ + g;
        float* xwoA = xw1 + (size_t)bA * S_ * G4_ + g;
        float* xwoB = xw1 + (size_t)bB * S_ * G4_ + g;
        float xwbufA[4], xwbufB[4];
#pragma unroll
        for (int j = 0; j < 4; j++) {
            xwbufA[j] = xwbA[(size_t)j * G4_];
            xwbufB[j] = xwbB[(size_t)j * G4_];
        }
        __syncthreads();

        for (int t = 0; t < S_; t += 4) {
#pragma unroll
            for (int j = 0; j < 4; j++) {
                const int tj = t + j;
                const int tn = tj + 4;
                float xvA = xwbufA[j], xvB = xwbufB[j];
                if (tn < S_) {
                    xwbufA[j] = xwbA[(size_t)tn * G4_];
                    xwbufB[j] = xwbB[(size_t)tn * G4_];
                }

                // ---- chain A: fused Wh0 & Wx1 dots over hA ----
                {
                    ull a0 = 0, a1 = 0, a2 = 0, a3 = 0;
                    ull q0 = 0, q1 = 0, q2 = 0, q3 = 0;
#pragma unroll
                    for (int k4 = 0; k4 < 16; k4 += 2) {
                        ulonglong2 hA2 = h4A[k4];
                        ulonglong2 hB2 = h4A[k4 + 1];
                        a0 = fma2(hA2.x, wA[2 * k4 + 0], a0);
                        q0 = fma2(hA2.x, wB[2 * k4 + 0], q0);
                        a1 = fma2(hA2.y, wA[2 * k4 + 1], a1);
                        q1 = fma2(hA2.y, wB[2 * k4 + 1], q1);
                        a2 = fma2(hB2.x, wA[2 * k4 + 2], a2);
                        q2 = fma2(hB2.x, wB[2 * k4 + 2], q2);
                        a3 = fma2(hB2.y, wA[2 * k4 + 3], a3);
                        q3 = fma2(hB2.y, wB[2 * k4 + 3], q3);
                    }
                    a0 = add2(add2(a0, a1), add2(a2, a3));
                    q0 = add2(add2(q0, q1), add2(q2, q3));
                    float2 sa = upk2(a0);
                    float2 sq = upk2(q0);
                    float pre = sa.x + sa.y + xvA;
                    gbufA[g] = (gtype == 2) ? tanh_fast(pre) : sig_fast(pre);
                    if (tj > 0) xwoA[(size_t)(tj - 1) * G4_] = sq.x + sq.y + b1g;
                }
                // ---- chain B ----
                {
                    ull a0 = 0, a1 = 0, a2 = 0, a3 = 0;
                    ull q0 = 0, q1 = 0, q2 = 0, q3 = 0;
#pragma unroll
                    for (int k4 = 0; k4 < 16; k4 += 2) {
                        ulonglong2 hA2 = h4B[k4];
                        ulonglong2 hB2 = h4B[k4 + 1];
                        a0 = fma2(hA2.x, wA[2 * k4 + 0], a0);
                        q0 = fma2(hA2.x, wB[2 * k4 + 0], q0);
                        a1 = fma2(hA2.y, wA[2 * k4 + 1], a1);
                        q1 = fma2(hA2.y, wB[2 * k4 + 1], q1);
                        a2 = fma2(hB2.x, wA[2 * k4 + 2], a2);
                        q2 = fma2(hB2.x, wB[2 * k4 + 2], q2);
                        a3 = fma2(hB2.y, wA[2 * k4 + 3], a3);
                        q3 = fma2(hB2.y, wB[2 * k4 + 3], q3);
                    }
                    a0 = add2(add2(a0, a1), add2(a2, a3));
                    q0 = add2(add2(q0, q1), add2(q2, q3));
                    float2 sa = upk2(a0);
                    float2 sq = upk2(q0);
                    float pre = sa.x + sa.y + xvB;
                    gbufB[g] = (gtype == 2) ? tanh_fast(pre) : sig_fast(pre);
                    if (tj > 0) xwoB[(size_t)(tj - 1) * G4_] = sq.x + sq.y + b1g;
                }
                __syncthreads();

                if (g < F_) {                       // chain A update
                    float iv = gbufA[g];
                    float fv = gbufA[g + 64];
                    float gg = gbufA[g + 128];
                    float ov = gbufA[g + 192];
                    cA = fv * cA + iv * gg;
                    hA_s[g] = ov * tanh_fast(cA);
                } else if (g < 2 * F_) {            // chain B update
                    int u = g - F_;
                    float iv = gbufB[u];
                    float fv = gbufB[u + 64];
                    float gg = gbufB[u + 128];
                    float ov = gbufB[u + 192];
                    cB = fv * cB + iv * gg;
                    hB_s[u] = ov * tanh_fast(cB);
                }
                __syncthreads();
            }
            if ((t & 4) && g == 0) {
                __threadfence();
                *(volatile int*)&prog[bA] = t + 3;
            }
        }
        // epilogue: publish xw1[S-1] for both chains from final h0[S-1]
        {
            ull q0 = 0, q1 = 0, q2 = 0, q3 = 0;
#pragma unroll
            for (int k4 = 0; k4 < 16; k4 += 2) {
                ulonglong2 hA2 = h4A[k4];
                ulonglong2 hB2 = h4A[k4 + 1];
                q0 = fma2(hA2.x, wB[2 * k4 + 0], q0);
                q1 = fma2(hA2.y, wB[2 * k4 + 1], q1);
                q2 = fma2(hB2.x, wB[2 * k4 + 2], q2);
                q3 = fma2(hB2.y, wB[2 * k4 + 3], q3);
            }
            q0 = add2(add2(q0, q1), add2(q2, q3));
            float2 sq = upk2(q0);
            xwoA[(size_t)(S_ - 1) * G4_] = sq.x + sq.y + b1g;
        }
        {
            ull q0 = 0, q1 = 0, q2 = 0, q3 = 0;
#pragma unroll
            for (int k4 = 0; k4 < 16; k4 += 2) {
                ulonglong2 hA2 = h4B[k4];
                ulonglong2 hB2 = h4B[k4 + 1];
                q0 = fma2(hA2.x, wB[2 * k4 + 0], q0);
                q1 = fma2(hA2.y, wB[2 * k4 + 1], q1);
                q2 = fma2(hB2.x, wB[2 * k4 + 2], q2);
                q3 = fma2(hB2.y, wB[2 * k4 + 3], q3);
            }
            q0 = add2(add2(q0, q1), add2(q2, q3));
            float2 sq = upk2(q0);
            xwoB[(size_t)(S_ - 1) * G4_] = sq.x + sq.y + b1g;
        }
        __syncthreads();
        if (g == 0) {
            __threadfence();
            *(volatile int*)&prog[bA] = S_;
        }
    } else {
        // ---------------- consumer: layer1 recurrence, two chains ----------
        ull w2[32];
#pragma unroll
        for (int k2 = 0; k2 < 32; k2++) {
            w2[k2] = pk2(Wh1[(size_t)(2 * k2) * G4_ + g],
                         Wh1[(size_t)(2 * k2 + 1) * G4_ + g]);
        }

        if (g < F_) { hA_s[g] = 0.0f; hB_s[g] = 0.0f; }
        float cA = 0.0f, cB = 0.0f;

        const float* xwbA = xw1 + (size_t)bA * S_ * G4_ + g;
        const float* xwbB = xw1 + (size_t)bB * S_ * G4_ + g;
        const volatile int* pf = &prog[bA];
        int seen = 0;

        {
            int need = (8 < S_) ? 8 : S_;
            while (seen < need) { seen = *pf; if (seen < need) __nanosleep(64); }
            __threadfence();
        }
        float xwbufA[4], xwbufB[4];
#pragma unroll
        for (int j = 0; j < 4; j++) {
            xwbufA[j] = __ldcg(xwbA + (size_t)j * G4_);
            xwbufB[j] = __ldcg(xwbB + (size_t)j * G4_);
        }
        __syncthreads();

        for (int t = 0; t < S_; t += 4) {
            int need = (t + 8 < S_) ? (t + 8) : S_;
            if (seen < need) {
                while (seen < need) { seen = *pf; if (seen < need) __nanosleep(64); }
                __threadfence();
            }
#pragma unroll
            for (int j = 0; j < 4; j++) {
                const int tn = t + 4 + j;
                float xvA = xwbufA[j], xvB = xwbufB[j];
                if (tn < S_) {
                    xwbufA[j] = __ldcg(xwbA + (size_t)tn * G4_);
                    xwbufB[j] = __ldcg(xwbB + (size_t)tn * G4_);
                }

                {
                    ull a0 = 0, a1 = 0, a2 = 0, a3 = 0;
#pragma unroll
                    for (int k4 = 0; k4 < 16; k4 += 2) {
                        ulonglong2 hA2 = h4A[k4];
                        ulonglong2 hB2 = h4A[k4 + 1];
                        a0 = fma2(hA2.x, w2[2 * k4 + 0], a0);
                        a1 = fma2(hA2.y, w2[2 * k4 + 1], a1);
                        a2 = fma2(hB2.x, w2[2 * k4 + 2], a2);
                        a3 = fma2(hB2.y, w2[2 * k4 + 3], a3);
                    }
                    a0 = add2(add2(a0, a1), add2(a2, a3));
                    float2 sv = upk2(a0);
                    float pre = sv.x + sv.y + xvA;
                    gbufA[g] = (gtype == 2) ? tanh_fast(pre) : sig_fast(pre);
                }
                {
                    ull a0 = 0, a1 = 0, a2 = 0, a3 = 0;
#pragma unroll
                    for (int k4 = 0; k4 < 16; k4 += 2) {
                        ulonglong2 hA2 = h4B[k4];
                        ulonglong2 hB2 = h4B[k4 + 1];
                        a0 = fma2(hA2.x, w2[2 * k4 + 0], a0);
                        a1 = fma2(hA2.y, w2[2 * k4 + 1], a1);
                        a2 = fma2(hB2.x, w2[2 * k4 + 2], a2);
                        a3 = fma2(hB2.y, w2[2 * k4 + 3], a3);
                    }
                    a0 = add2(add2(a0, a1), add2(a2, a3));
                    float2 sv = upk2(a0);
                    float pre = sv.x + sv.y + xvB;
                    gbufB[g] = (gtype == 2) ? tanh_fast(pre) : sig_fast(pre);
                }
                __syncthreads();

                if (g < F_) {
                    float iv = gbufA[g];
                    float fv = gbufA[g + 64];
                    float gg = gbufA[g + 128];
                    float ov = gbufA[g + 192];
                    cA = fv * cA + iv * gg;
                    hA_s[g] = ov * tanh_fast(cA);
                } else if (g < 2 * F_) {
                    int u = g - F_;
                    float iv = gbufB[u];
                    float fv = gbufB[u + 64];
                    float gg = gbufB[u + 128];
                    float ov = gbufB[u + 192];
                    cB = fv * cB + iv * gg;
                    hB_s[u] = ov * tanh_fast(cB);
                }
                __syncthreads();
            }
        }
        if (g < F_) c_final[bA * F_ + g] = cA;
        else if (g < 2 * F_) c_final[bB * F_ + (g - F_)] = cB;
    }
}

// ---------------------------------------------------------------------------
// Tiny dense head
// ---------------------------------------------------------------------------
__global__ void dense_head(const float* __restrict__ cf,
                           const float* __restrict__ wd,
                           const float* __restrict__ bd,
                           float* __restrict__ out) {
    int t = threadIdx.x;
    if (t >= B_ * 10) return;
    int b = t / 10, n = t % 10;
    float s = bd[n];
#pragma unroll
    for (int k = 0; k < F_; k++) s += cf[b * F_ + k] * wd[k * 10 + n];
    out[b * 10 + n] = s;
}

// ---------------------------------------------------------------------------
extern "C" void kernel_launch(void* const* d_in, const int* in_sizes, int n_in,
                              void* d_out, int out_size) {
    const float* x       = (const float*)d_in[0];
    const float* conv_w0 = (const float*)d_in[1];
    const float* conv_b0 = (const float*)d_in[2];
    const float* conv_w1 = (const float*)d_in[3];
    const float* conv_b1 = (const float*)d_in[4];
    const float* conv_w2 = (const float*)d_in[5];
    const float* conv_b2 = (const float*)d_in[6];
    const float* Wx0     = (const float*)d_in[7];
    const float* Wh0     = (const float*)d_in[8];
    const float* b0      = (const float*)d_in[9];
    const float* Wx1     = (const float*)d_in[10];
    const float* Wh1     = (const float*)d_in[11];
    const float* b1      = (const float*)d_in[12];
    const float* dense_w = (const float*)d_in[13];
    const float* dense_b = (const float*)d_in[14];
    float* out = (float*)d_out;

    void *pA, *pB, *pXW0, *pXW1, *pPR, *pCF;
    cudaGetSymbolAddress(&pA, g_bufA);
    cudaGetSymbolAddress(&pB, g_bufB);
    cudaGetSymbolAddress(&pXW0, g_xw0);
    cudaGetSymbolAddress(&pXW1, g_xw1);
    cudaGetSymbolAddress(&pPR, g_prog);
    cudaGetSymbolAddress(&pCF, g_cfinal);
    float* bufA = (float*)pA;
    float* bufB = (float*)pB;
    float* xw0  = (float*)pXW0;
    float* xw1  = (float*)pXW1;
    int*   prog = (int*)pPR;
    float* cfin = (float*)pCF;

    dim3 convGrid(S_ / 64, 1, B_);
    dim3 gemmGrid(S_ / 64, G4_ / 64, B_);

    // CNN stack
    conv_gemm<3, true><<<convGrid, 256>>>(x, conv_w0, conv_b0, bufA, 128, 64);
    conv_gemm<3, true><<<convGrid, 256>>>(bufA, conv_w1, conv_b1, bufB, 64, 64);
    conv_gemm<3, true><<<convGrid, 256>>>(bufB, conv_w2, conv_b2, bufA, 64, 64);

    // LSTM layer0 input projection (big parallel GEMM)
    conv_gemm<1, false><<<gemmGrid, 256>>>(bufA, Wx0, b0, xw0, 64, 256);

    // Pipelined 2-layer recurrence, 2 chains per CTA
    lstm_pipe<<<2 * 32, 256>>>(xw0, Wh0, Wx1, b1, Wh1, xw1, prog, cfin);

    // Dense head
    dense_head<<<1, B_ * 10>>>(cfin, dense_w, dense_b, out);
}

// round 10
// speedup vs baseline: 1.5896x; 1.5896x over previous
#include <cuda_runtime.h>
#include <cstdint>

#define B_    64
#define S_    4096
#define F_    64
#define G4_   256   // 4 * F_

// ---------------- scratch (no cudaMalloc allowed) ----------------
__device__ float g_bufA[(size_t)B_ * S_ * F_];    // conv0 out / conv2 out
__device__ float g_bufB[(size_t)B_ * S_ * F_];    // conv1 out
__device__ float g_xw0[(size_t)B_ * S_ * G4_];    // layer0 gate pre-activations
__device__ float g_xw1[(size_t)B_ * S_ * G4_];    // layer1 gate pre-activations
__device__ int   g_prog[B_];                      // producer progress flags
__device__ float g_cfinal[B_ * F_];

typedef unsigned long long ull;

// ---------------- packed f32x2 helpers (sm_103a FFMA2 path) ----------------
__device__ __forceinline__ ull fma2(ull a, ull b, ull c) {
    ull d;
    asm("fma.rn.f32x2 %0, %1, %2, %3;" : "=l"(d) : "l"(a), "l"(b), "l"(c));
    return d;
}
__device__ __forceinline__ ull add2(ull a, ull b) {
    ull d;
    asm("add.rn.f32x2 %0, %1, %2;" : "=l"(d) : "l"(a), "l"(b));
    return d;
}
__device__ __forceinline__ ull dup2(float a) {
    ull d;
    asm("mov.b64 %0, {%1, %1};" : "=l"(d) : "f"(a));
    return d;
}
__device__ __forceinline__ ull pk2(float lo, float hi) {
    ull d;
    asm("mov.b64 %0, {%1, %2};" : "=l"(d) : "f"(lo), "f"(hi));
    return d;
}
__device__ __forceinline__ float2 upk2(ull v) {
    float2 r;
    asm("mov.b64 {%0, %1}, %2;" : "=f"(r.x), "=f"(r.y) : "l"(v));
    return r;
}

// HW tanh.approx (single MUFU)
__device__ __forceinline__ float tanh_fast(float x) {
    float r;
    asm("tanh.approx.f32 %0, %1;" : "=f"(r) : "f"(x));
    return r;
}
__device__ __forceinline__ float sig_fast(float x) {
    return fmaf(0.5f, tanh_fast(0.5f * x), 0.5f);
}

// ---------------------------------------------------------------------------
// Fused conv1d / GEMM kernel (unchanged, known-good R2/R6 version).
// ---------------------------------------------------------------------------
template <int KW, bool RELU>
__global__ void __launch_bounds__(256)
conv_gemm(const float* __restrict__ xin, const float* __restrict__ w,
          const float* __restrict__ bias, float* __restrict__ out,
          int Cin, int Cout) {
    constexpr int PAD = KW / 2;
    constexpr int RX = 64 + KW - 1;

    __shared__ __align__(16) float xs[66][16];
    __shared__ __align__(16) float ws[KW][16][64];

    const int tid = threadIdx.x;
    const int tx = tid & 15;
    const int ty = tid >> 4;
    const int s0 = blockIdx.x * 64;
    const int co0 = blockIdx.y * 64;
    const int b = blockIdx.z;

    const float* xb = xin + (size_t)b * S_ * Cin;

    ull a01[4], a23[4];
#pragma unroll
    for (int i = 0; i < 4; i++) { a01[i] = 0ull; a23[i] = 0ull; }

    for (int ck = 0; ck < Cin; ck += 16) {
        __syncthreads();
        for (int idx = tid; idx < RX * 16; idx += 256) {
            int r = idx >> 4, k = idx & 15;
            int sg = s0 + r - PAD;
            float v = 0.0f;
            if (sg >= 0 && sg < S_) v = xb[(size_t)sg * Cin + ck + k];
            xs[r][k] = v;
        }
        for (int idx = tid; idx < KW * 16 * 64; idx += 256) {
            int c = idx & 63, k = (idx >> 6) & 15, dk = idx >> 10;
            ws[dk][k][c] = w[((size_t)dk * Cin + (ck + k)) * Cout + co0 + c];
        }
        __syncthreads();

#pragma unroll
        for (int dk = 0; dk < KW; dk++) {
#pragma unroll
            for (int k = 0; k < 16; k++) {
                ulonglong2 wv =
                    *reinterpret_cast<const ulonglong2*>(&ws[dk][k][tx << 2]);
#pragma unroll
                for (int i = 0; i < 4; i++) {
                    ull av = dup2(xs[ty * 4 + i + dk][k]);
                    a01[i] = fma2(av, wv.x, a01[i]);
                    a23[i] = fma2(av, wv.y, a23[i]);
                }
            }
        }
    }

    const int c0 = co0 + (tx << 2);
    const float bb0 = bias[c0 + 0], bb1 = bias[c0 + 1];
    const float bb2 = bias[c0 + 2], bb3 = bias[c0 + 3];
#pragma unroll
    for (int i = 0; i < 4; i++) {
        float2 v01 = upk2(a01[i]);
        float2 v23 = upk2(a23[i]);
        float4 o;
        o.x = v01.x + bb0; o.y = v01.y + bb1;
        o.z = v23.x + bb2; o.w = v23.y + bb3;
        if (RELU) {
            o.x = fmaxf(o.x, 0.0f); o.y = fmaxf(o.y, 0.0f);
            o.z = fmaxf(o.z, 0.0f); o.w = fmaxf(o.w, 0.0f);
        }
        int sg = s0 + ty * 4 + i;
        *reinterpret_cast<float4*>(&out[((size_t)b * S_ + sg) * Cout + c0]) = o;
    }
}

// ---------------------------------------------------------------------------
// Pipelined 2-layer LSTM recurrence, TWO independent batch chains per CTA.
// Blocks 0..31: producers, batches (2p, 2p+1), layer 0. Fused Wh0/Wx1 dots
// per chain (R6 scheme), publish xw1 for both, flag on prog[2p].
// Blocks 32..63: consumers, same batch pair, layer 1.
// Chain A's dependency tail overlaps chain B's issue; barriers amortized 2x.
// Weight columns are register-resident and SHARED between the two chains.
// ---------------------------------------------------------------------------
__global__ void __launch_bounds__(256, 1)
lstm_pipe(const float* __restrict__ xw0, const float* __restrict__ Wh0,
          const float* __restrict__ Wx1, const float* __restrict__ b1v,
          const float* __restrict__ Wh1,
          float* __restrict__ xw1, int* __restrict__ prog,
          float* __restrict__ c_final) {
    const int p = blockIdx.x & 31;
    const bool producer = blockIdx.x < 32;
    const int bA = 2 * p, bB = 2 * p + 1;
    const int g = threadIdx.x;
    const int gtype = g >> 6;

    __shared__ __align__(16) float hA_s[F_], hB_s[F_];
    __shared__ float gbufA[G4_], gbufB[G4_];

    const ulonglong2* h4A = reinterpret_cast<const ulonglong2*>(hA_s);
    const ulonglong2* h4B = reinterpret_cast<const ulonglong2*>(hB_s);

    if (producer) {
        ull wA[32], wB[32];
#pragma unroll
        for (int k2 = 0; k2 < 32; k2++) {
            wA[k2] = pk2(Wh0[(size_t)(2 * k2) * G4_ + g],
                         Wh0[(size_t)(2 * k2 + 1) * G4_ + g]);
            wB[k2] = pk2(Wx1[(size_t)(2 * k2) * G4_ + g],
                         Wx1[(size_t)(2 * k2 + 1) * G4_ + g]);
        }
        const float b1g = b1v[g];

        if (g < F_) { hA_s[g] = 0.0f; hB_s[g] = 0.0f; }
        float cA = 0.0f, cB = 0.0f;

        const float* xwbA = xw0 + (size_t)bA * S_ * G4_ + g;
        const float* xwbB = xw0 + (size_t)bB * S_ * G4_ + g;
        float* xwoA = xw1 + (size_t)bA * S_ * G4_ + g;
        float* xwoB = xw1 + (size_t)bB * S_ * G4_ + g;
        float xwbufA[4], xwbufB[4];
#pragma unroll
        for (int j = 0; j < 4; j++) {
            xwbufA[j] = xwbA[(size_t)j * G4_];
            xwbufB[j] = xwbB[(size_t)j * G4_];
        }
        __syncthreads();

        for (int t = 0; t < S_; t += 4) {
#pragma unroll
            for (int j = 0; j < 4; j++) {
                const int tj = t + j;
                const int tn = tj + 4;
                float xvA = xwbufA[j], xvB = xwbufB[j];
                if (tn < S_) {
                    xwbufA[j] = xwbA[(size_t)tn * G4_];
                    xwbufB[j] = xwbB[(size_t)tn * G4_];
                }

                // ---- chain A: fused Wh0 & Wx1 dots over hA ----
                {
                    ull a0 = 0, a1 = 0, a2 = 0, a3 = 0;
                    ull q0 = 0, q1 = 0, q2 = 0, q3 = 0;
#pragma unroll
                    for (int k4 = 0; k4 < 16; k4 += 2) {
                        ulonglong2 hA2 = h4A[k4];
                        ulonglong2 hB2 = h4A[k4 + 1];
                        a0 = fma2(hA2.x, wA[2 * k4 + 0], a0);
                        q0 = fma2(hA2.x, wB[2 * k4 + 0], q0);
                        a1 = fma2(hA2.y, wA[2 * k4 + 1], a1);
                        q1 = fma2(hA2.y, wB[2 * k4 + 1], q1);
                        a2 = fma2(hB2.x, wA[2 * k4 + 2], a2);
                        q2 = fma2(hB2.x, wB[2 * k4 + 2], q2);
                        a3 = fma2(hB2.y, wA[2 * k4 + 3], a3);
                        q3 = fma2(hB2.y, wB[2 * k4 + 3], q3);
                    }
                    a0 = add2(add2(a0, a1), add2(a2, a3));
                    q0 = add2(add2(q0, q1), add2(q2, q3));
                    float2 sa = upk2(a0);
                    float2 sq = upk2(q0);
                    float pre = sa.x + sa.y + xvA;
                    gbufA[g] = (gtype == 2) ? tanh_fast(pre) : sig_fast(pre);
                    if (tj > 0) xwoA[(size_t)(tj - 1) * G4_] = sq.x + sq.y + b1g;
                }
                // ---- chain B ----
                {
                    ull a0 = 0, a1 = 0, a2 = 0, a3 = 0;
                    ull q0 = 0, q1 = 0, q2 = 0, q3 = 0;
#pragma unroll
                    for (int k4 = 0; k4 < 16; k4 += 2) {
                        ulonglong2 hA2 = h4B[k4];
                        ulonglong2 hB2 = h4B[k4 + 1];
                        a0 = fma2(hA2.x, wA[2 * k4 + 0], a0);
                        q0 = fma2(hA2.x, wB[2 * k4 + 0], q0);
                        a1 = fma2(hA2.y, wA[2 * k4 + 1], a1);
                        q1 = fma2(hA2.y, wB[2 * k4 + 1], q1);
                        a2 = fma2(hB2.x, wA[2 * k4 + 2], a2);
                        q2 = fma2(hB2.x, wB[2 * k4 + 2], q2);
                        a3 = fma2(hB2.y, wA[2 * k4 + 3], a3);
                        q3 = fma2(hB2.y, wB[2 * k4 + 3], q3);
                    }
                    a0 = add2(add2(a0, a1), add2(a2, a3));
                    q0 = add2(add2(q0, q1), add2(q2, q3));
                    float2 sa = upk2(a0);
                    float2 sq = upk2(q0);
                    float pre = sa.x + sa.y + xvB;
                    gbufB[g] = (gtype == 2) ? tanh_fast(pre) : sig_fast(pre);
                    if (tj > 0) xwoB[(size_t)(tj - 1) * G4_] = sq.x + sq.y + b1g;
                }
                __syncthreads();

                if (g < F_) {                       // chain A update
                    float iv = gbufA[g];
                    float fv = gbufA[g + 64];
                    float gg = gbufA[g + 128];
                    float ov = gbufA[g + 192];
                    cA = fv * cA + iv * gg;
                    hA_s[g] = ov * tanh_fast(cA);
                } else if (g < 2 * F_) {            // chain B update
                    int u = g - F_;
                    float iv = gbufB[u];
                    float fv = gbufB[u + 64];
                    float gg = gbufB[u + 128];
                    float ov = gbufB[u + 192];
                    cB = fv * cB + iv * gg;
                    hB_s[u] = ov * tanh_fast(cB);
                }
                __syncthreads();
            }
            if ((t & 4) && g == 0) {
                __threadfence();
                *(volatile int*)&prog[bA] = t + 3;
            }
        }
        // epilogue: publish xw1[S-1] for both chains from final h0[S-1]
        {
            ull q0 = 0, q1 = 0, q2 = 0, q3 = 0;
#pragma unroll
            for (int k4 = 0; k4 < 16; k4 += 2) {
                ulonglong2 hA2 = h4A[k4];
                ulonglong2 hB2 = h4A[k4 + 1];
                q0 = fma2(hA2.x, wB[2 * k4 + 0], q0);
                q1 = fma2(hA2.y, wB[2 * k4 + 1], q1);
                q2 = fma2(hB2.x, wB[2 * k4 + 2], q2);
                q3 = fma2(hB2.y, wB[2 * k4 + 3], q3);
            }
            q0 = add2(add2(q0, q1), add2(q2, q3));
            float2 sq = upk2(q0);
            xwoA[(size_t)(S_ - 1) * G4_] = sq.x + sq.y + b1g;
        }
        {
            ull q0 = 0, q1 = 0, q2 = 0, q3 = 0;
#pragma unroll
            for (int k4 = 0; k4 < 16; k4 += 2) {
                ulonglong2 hA2 = h4B[k4];
                ulonglong2 hB2 = h4B[k4 + 1];
                q0 = fma2(hA2.x, wB[2 * k4 + 0], q0);
                q1 = fma2(hA2.y, wB[2 * k4 + 1], q1);
                q2 = fma2(hB2.x, wB[2 * k4 + 2], q2);
                q3 = fma2(hB2.y, wB[2 * k4 + 3], q3);
            }
            q0 = add2(add2(q0, q1), add2(q2, q3));
            float2 sq = upk2(q0);
            xwoB[(size_t)(S_ - 1) * G4_] = sq.x + sq.y + b1g;
        }
        __syncthreads();
        if (g == 0) {
            __threadfence();
            *(volatile int*)&prog[bA] = S_;
        }
    } else {
        // ---------------- consumer: layer1 recurrence, two chains ----------
        ull w2[32];
#pragma unroll
        for (int k2 = 0; k2 < 32; k2++) {
            w2[k2] = pk2(Wh1[(size_t)(2 * k2) * G4_ + g],
                         Wh1[(size_t)(2 * k2 + 1) * G4_ + g]);
        }

        if (g < F_) { hA_s[g] = 0.0f; hB_s[g] = 0.0f; }
        float cA = 0.0f, cB = 0.0f;

        const float* xwbA = xw1 + (size_t)bA * S_ * G4_ + g;
        const float* xwbB = xw1 + (size_t)bB * S_ * G4_ + g;
        const volatile int* pf = &prog[bA];
        int seen = 0;

        {
            int need = (8 < S_) ? 8 : S_;
            while (seen < need) { seen = *pf; if (seen < need) __nanosleep(64); }
            __threadfence();
        }
        float xwbufA[4], xwbufB[4];
#pragma unroll
        for (int j = 0; j < 4; j++) {
            xwbufA[j] = __ldcg(xwbA + (size_t)j * G4_);
            xwbufB[j] = __ldcg(xwbB + (size_t)j * G4_);
        }
        __syncthreads();

        for (int t = 0; t < S_; t += 4) {
            int need = (t + 8 < S_) ? (t + 8) : S_;
            if (seen < need) {
                while (seen < need) { seen = *pf; if (seen < need) __nanosleep(64); }
                __threadfence();
            }
#pragma unroll
            for (int j = 0; j < 4; j++) {
                const int tn = t + 4 + j;
                float xvA = xwbufA[j], xvB = xwbufB[j];
                if (tn < S_) {
                    xwbufA[j] = __ldcg(xwbA + (size_t)tn * G4_);
                    xwbufB[j] = __ldcg(xwbB + (size_t)tn * G4_);
                }

                {
                    ull a0 = 0, a1 = 0, a2 = 0, a3 = 0;
#pragma unroll
                    for (int k4 = 0; k4 < 16; k4 += 2) {
                        ulonglong2 hA2 = h4A[k4];
                        ulonglong2 hB2 = h4A[k4 + 1];
                        a0 = fma2(hA2.x, w2[2 * k4 + 0], a0);
                        a1 = fma2(hA2.y, w2[2 * k4 + 1], a1);
                        a2 = fma2(hB2.x, w2[2 * k4 + 2], a2);
                        a3 = fma2(hB2.y, w2[2 * k4 + 3], a3);
                    }
                    a0 = add2(add2(a0, a1), add2(a2, a3));
                    float2 sv = upk2(a0);
                    float pre = sv.x + sv.y + xvA;
                    gbufA[g] = (gtype == 2) ? tanh_fast(pre) : sig_fast(pre);
                }
                {
                    ull a0 = 0, a1 = 0, a2 = 0, a3 = 0;
#pragma unroll
                    for (int k4 = 0; k4 < 16; k4 += 2) {
                        ulonglong2 hA2 = h4B[k4];
                        ulonglong2 hB2 = h4B[k4 + 1];
                        a0 = fma2(hA2.x, w2[2 * k4 + 0], a0);
                        a1 = fma2(hA2.y, w2[2 * k4 + 1], a1);
                        a2 = fma2(hB2.x, w2[2 * k4 + 2], a2);
                        a3 = fma2(hB2.y, w2[2 * k4 + 3], a3);
                    }
                    a0 = add2(add2(a0, a1), add2(a2, a3));
                    float2 sv = upk2(a0);
                    float pre = sv.x + sv.y + xvB;
                    gbufB[g] = (gtype == 2) ? tanh_fast(pre) : sig_fast(pre);
                }
                __syncthreads();

                if (g < F_) {
                    float iv = gbufA[g];
                    float fv = gbufA[g + 64];
                    float gg = gbufA[g + 128];
                    float ov = gbufA[g + 192];
                    cA = fv * cA + iv * gg;
                    hA_s[g] = ov * tanh_fast(cA);
                } else if (g < 2 * F_) {
                    int u = g - F_;
                    float iv = gbufB[u];
                    float fv = gbufB[u + 64];
                    float gg = gbufB[u + 128];
                    float ov = gbufB[u + 192];
                    cB = fv * cB + iv * gg;
                    hB_s[u] = ov * tanh_fast(cB);
                }
                __syncthreads();
            }
        }
        if (g < F_) c_final[bA * F_ + g] = cA;
        else if (g < 2 * F_) c_final[bB * F_ + (g - F_)] = cB;
    }
}

// ---------------------------------------------------------------------------
// Tiny dense head
// ---------------------------------------------------------------------------
__global__ void dense_head(const float* __restrict__ cf,
                           const float* __restrict__ wd,
                           const float* __restrict__ bd,
                           float* __restrict__ out) {
    int t = threadIdx.x;
    if (t >= B_ * 10) return;
    int b = t / 10, n = t % 10;
    float s = bd[n];
#pragma unroll
    for (int k = 0; k < F_; k++) s += cf[b * F_ + k] * wd[k * 10 + n];
    out[b * 10 + n] = s;
}

// ---------------------------------------------------------------------------
extern "C" void kernel_launch(void* const* d_in, const int* in_sizes, int n_in,
                              void* d_out, int out_size) {
    const float* x       = (const float*)d_in[0];
    const float* conv_w0 = (const float*)d_in[1];
    const float* conv_b0 = (const float*)d_in[2];
    const float* conv_w1 = (const float*)d_in[3];
    const float* conv_b1 = (const float*)d_in[4];
    const float* conv_w2 = (const float*)d_in[5];
    const float* conv_b2 = (const float*)d_in[6];
    const float* Wx0     = (const float*)d_in[7];
    const float* Wh0     = (const float*)d_in[8];
    const float* b0      = (const float*)d_in[9];
    const float* Wx1     = (const float*)d_in[10];
    const float* Wh1     = (const float*)d_in[11];
    const float* b1      = (const float*)d_in[12];
    const float* dense_w = (const float*)d_in[13];
    const float* dense_b = (const float*)d_in[14];
    float* out = (float*)d_out;

    void *pA, *pB, *pXW0, *pXW1, *pPR, *pCF;
    cudaGetSymbolAddress(&pA, g_bufA);
    cudaGetSymbolAddress(&pB, g_bufB);
    cudaGetSymbolAddress(&pXW0, g_xw0);
    cudaGetSymbolAddress(&pXW1, g_xw1);
    cudaGetSymbolAddress(&pPR, g_prog);
    cudaGetSymbolAddress(&pCF, g_cfinal);
    float* bufA = (float*)pA;
    float* bufB = (float*)pB;
    float* xw0  = (float*)pXW0;
    float* xw1  = (float*)pXW1;
    int*   prog = (int*)pPR;
    float* cfin = (float*)pCF;

    dim3 convGrid(S_ / 64, 1, B_);
    dim3 gemmGrid(S_ / 64, G4_ / 64, B_);

    // CNN stack
    conv_gemm<3, true><<<convGrid, 256>>>(x, conv_w0, conv_b0, bufA, 128, 64);
    conv_gemm<3, true><<<convGrid, 256>>>(bufA, conv_w1, conv_b1, bufB, 64, 64);
    conv_gemm<3, true><<<convGrid, 256>>>(bufB, conv_w2, conv_b2, bufA, 64, 64);

    // LSTM layer0 input projection (big parallel GEMM)
    conv_gemm<1, false><<<gemmGrid, 256>>>(bufA, Wx0, b0, xw0, 64, 256);

    // Pipelined 2-layer recurrence, 2 chains per CTA
    lstm_pipe<<<2 * 32, 256>>>(xw0, Wh0, Wx1, b1, Wh1, xw1, prog, cfin);

    // Dense head
    dense_head<<<1, B_ * 10>>>(cfin, dense_w, dense_b, out);
}

// round 11
// speedup vs baseline: 1.5899x; 1.0002x over previous
#include <cuda_runtime.h>
#include <cstdint>

#define B_    64
#define S_    4096
#define F_    64
#define G4_   256   // 4 * F_

// ---------------- scratch (no cudaMalloc allowed) ----------------
__device__ float g_bufA[(size_t)B_ * S_ * F_];    // conv0 out / conv2 out
__device__ float g_bufB[(size_t)B_ * S_ * F_];    // conv1 out
__device__ float g_xw0[(size_t)B_ * S_ * G4_];    // layer0 gate pre-activations
__device__ float g_xw1[(size_t)B_ * S_ * G4_];    // layer1 gate pre-activations
__device__ int   g_prog[B_];                      // producer progress flags
__device__ float g_cfinal[B_ * F_];

typedef unsigned long long ull;

// ---------------- packed f32x2 helpers (sm_103a FFMA2 path) ----------------
__device__ __forceinline__ ull fma2(ull a, ull b, ull c) {
    ull d;
    asm("fma.rn.f32x2 %0, %1, %2, %3;" : "=l"(d) : "l"(a), "l"(b), "l"(c));
    return d;
}
__device__ __forceinline__ ull add2(ull a, ull b) {
    ull d;
    asm("add.rn.f32x2 %0, %1, %2;" : "=l"(d) : "l"(a), "l"(b));
    return d;
}
__device__ __forceinline__ ull dup2(float a) {
    ull d;
    asm("mov.b64 %0, {%1, %1};" : "=l"(d) : "f"(a));
    return d;
}
__device__ __forceinline__ ull pk2(float lo, float hi) {
    ull d;
    asm("mov.b64 %0, {%1, %2};" : "=l"(d) : "f"(lo), "f"(hi));
    return d;
}
__device__ __forceinline__ float2 upk2(ull v) {
    float2 r;
    asm("mov.b64 {%0, %1}, %2;" : "=f"(r.x), "=f"(r.y) : "l"(v));
    return r;
}

// HW tanh.approx (single MUFU)
__device__ __forceinline__ float tanh_fast(float x) {
    float r;
    asm("tanh.approx.f32 %0, %1;" : "=f"(r) : "f"(x));
    return r;
}
__device__ __forceinline__ float sig_fast(float x) {
    return fmaf(0.5f, tanh_fast(0.5f * x), 0.5f);
}

// ---------------------------------------------------------------------------
// Fused conv1d / GEMM kernel (unchanged, known-good R2/R6 version).
// ---------------------------------------------------------------------------
template <int KW, bool RELU>
__global__ void __launch_bounds__(256)
conv_gemm(const float* __restrict__ xin, const float* __restrict__ w,
          const float* __restrict__ bias, float* __restrict__ out,
          int Cin, int Cout) {
    constexpr int PAD = KW / 2;
    constexpr int RX = 64 + KW - 1;

    __shared__ __align__(16) float xs[66][16];
    __shared__ __align__(16) float ws[KW][16][64];

    const int tid = threadIdx.x;
    const int tx = tid & 15;
    const int ty = tid >> 4;
    const int s0 = blockIdx.x * 64;
    const int co0 = blockIdx.y * 64;
    const int b = blockIdx.z;

    const float* xb = xin + (size_t)b * S_ * Cin;

    ull a01[4], a23[4];
#pragma unroll
    for (int i = 0; i < 4; i++) { a01[i] = 0ull; a23[i] = 0ull; }

    for (int ck = 0; ck < Cin; ck += 16) {
        __syncthreads();
        for (int idx = tid; idx < RX * 16; idx += 256) {
            int r = idx >> 4, k = idx & 15;
            int sg = s0 + r - PAD;
            float v = 0.0f;
            if (sg >= 0 && sg < S_) v = xb[(size_t)sg * Cin + ck + k];
            xs[r][k] = v;
        }
        for (int idx = tid; idx < KW * 16 * 64; idx += 256) {
            int c = idx & 63, k = (idx >> 6) & 15, dk = idx >> 10;
            ws[dk][k][c] = w[((size_t)dk * Cin + (ck + k)) * Cout + co0 + c];
        }
        __syncthreads();

#pragma unroll
        for (int dk = 0; dk < KW; dk++) {
#pragma unroll
            for (int k = 0; k < 16; k++) {
                ulonglong2 wv =
                    *reinterpret_cast<const ulonglong2*>(&ws[dk][k][tx << 2]);
#pragma unroll
                for (int i = 0; i < 4; i++) {
                    ull av = dup2(xs[ty * 4 + i + dk][k]);
                    a01[i] = fma2(av, wv.x, a01[i]);
                    a23[i] = fma2(av, wv.y, a23[i]);
                }
            }
        }
    }

    const int c0 = co0 + (tx << 2);
    const float bb0 = bias[c0 + 0], bb1 = bias[c0 + 1];
    const float bb2 = bias[c0 + 2], bb3 = bias[c0 + 3];
#pragma unroll
    for (int i = 0; i < 4; i++) {
        float2 v01 = upk2(a01[i]);
        float2 v23 = upk2(a23[i]);
        float4 o;
        o.x = v01.x + bb0; o.y = v01.y + bb1;
        o.z = v23.x + bb2; o.w = v23.y + bb3;
        if (RELU) {
            o.x = fmaxf(o.x, 0.0f); o.y = fmaxf(o.y, 0.0f);
            o.z = fmaxf(o.z, 0.0f); o.w = fmaxf(o.w, 0.0f);
        }
        int sg = s0 + ty * 4 + i;
        *reinterpret_cast<float4*>(&out[((size_t)b * S_ + sg) * Cout + c0]) = o;
    }
}

// ---------------------------------------------------------------------------
// Pipelined 2-layer LSTM recurrence, TWO independent batch chains per CTA.
// Blocks 0..31: producers, batches (2p, 2p+1), layer 0. Fused Wh0/Wx1 dots
// per chain (R6 scheme), publish xw1 for both, flag on prog[2p].
// Blocks 32..63: consumers, same batch pair, layer 1.
// Chain A's dependency tail overlaps chain B's issue; barriers amortized 2x.
// Weight columns are register-resident and SHARED between the two chains.
// ---------------------------------------------------------------------------
__global__ void __launch_bounds__(256, 1)
lstm_pipe(const float* __restrict__ xw0, const float* __restrict__ Wh0,
          const float* __restrict__ Wx1, const float* __restrict__ b1v,
          const float* __restrict__ Wh1,
          float* __restrict__ xw1, int* __restrict__ prog,
          float* __restrict__ c_final) {
    const int p = blockIdx.x & 31;
    const bool producer = blockIdx.x < 32;
    const int bA = 2 * p, bB = 2 * p + 1;
    const int g = threadIdx.x;
    const int gtype = g >> 6;

    __shared__ __align__(16) float hA_s[F_], hB_s[F_];
    __shared__ float gbufA[G4_], gbufB[G4_];

    const ulonglong2* h4A = reinterpret_cast<const ulonglong2*>(hA_s);
    const ulonglong2* h4B = reinterpret_cast<const ulonglong2*>(hB_s);

    if (producer) {
        ull wA[32], wB[32];
#pragma unroll
        for (int k2 = 0; k2 < 32; k2++) {
            wA[k2] = pk2(Wh0[(size_t)(2 * k2) * G4_ + g],
                         Wh0[(size_t)(2 * k2 + 1) * G4_ + g]);
            wB[k2] = pk2(Wx1[(size_t)(2 * k2) * G4_ + g],
                         Wx1[(size_t)(2 * k2 + 1) * G4_ + g]);
        }
        const float b1g = b1v[g];

        if (g < F_) { hA_s[g] = 0.0f; hB_s[g] = 0.0f; }
        float cA = 0.0f, cB = 0.0f;

        const float* xwbA = xw0 + (size_t)bA * S_ * G4_ + g;
        const float* xwbB = xw0 + (size_t)bB * S_ * G4_ + g;
        float* xwoA = xw1 + (size_t)bA * S_ * G4_ + g;
        float* xwoB = xw1 + (size_t)bB * S_ * G4_ + g;
        float xwbufA[4], xwbufB[4];
#pragma unroll
        for (int j = 0; j < 4; j++) {
            xwbufA[j] = xwbA[(size_t)j * G4_];
            xwbufB[j] = xwbB[(size_t)j * G4_];
        }
        __syncthreads();

        for (int t = 0; t < S_; t += 4) {
#pragma unroll
            for (int j = 0; j < 4; j++) {
                const int tj = t + j;
                const int tn = tj + 4;
                float xvA = xwbufA[j], xvB = xwbufB[j];
                if (tn < S_) {
                    xwbufA[j] = xwbA[(size_t)tn * G4_];
                    xwbufB[j] = xwbB[(size_t)tn * G4_];
                }

                // ---- chain A: fused Wh0 & Wx1 dots over hA ----
                {
                    ull a0 = 0, a1 = 0, a2 = 0, a3 = 0;
                    ull q0 = 0, q1 = 0, q2 = 0, q3 = 0;
#pragma unroll
                    for (int k4 = 0; k4 < 16; k4 += 2) {
                        ulonglong2 hA2 = h4A[k4];
                        ulonglong2 hB2 = h4A[k4 + 1];
                        a0 = fma2(hA2.x, wA[2 * k4 + 0], a0);
                        q0 = fma2(hA2.x, wB[2 * k4 + 0], q0);
                        a1 = fma2(hA2.y, wA[2 * k4 + 1], a1);
                        q1 = fma2(hA2.y, wB[2 * k4 + 1], q1);
                        a2 = fma2(hB2.x, wA[2 * k4 + 2], a2);
                        q2 = fma2(hB2.x, wB[2 * k4 + 2], q2);
                        a3 = fma2(hB2.y, wA[2 * k4 + 3], a3);
                        q3 = fma2(hB2.y, wB[2 * k4 + 3], q3);
                    }
                    a0 = add2(add2(a0, a1), add2(a2, a3));
                    q0 = add2(add2(q0, q1), add2(q2, q3));
                    float2 sa = upk2(a0);
                    float2 sq = upk2(q0);
                    float pre = sa.x + sa.y + xvA;
                    gbufA[g] = (gtype == 2) ? tanh_fast(pre) : sig_fast(pre);
                    if (tj > 0) xwoA[(size_t)(tj - 1) * G4_] = sq.x + sq.y + b1g;
                }
                // ---- chain B ----
                {
                    ull a0 = 0, a1 = 0, a2 = 0, a3 = 0;
                    ull q0 = 0, q1 = 0, q2 = 0, q3 = 0;
#pragma unroll
                    for (int k4 = 0; k4 < 16; k4 += 2) {
                        ulonglong2 hA2 = h4B[k4];
                        ulonglong2 hB2 = h4B[k4 + 1];
                        a0 = fma2(hA2.x, wA[2 * k4 + 0], a0);
                        q0 = fma2(hA2.x, wB[2 * k4 + 0], q0);
                        a1 = fma2(hA2.y, wA[2 * k4 + 1], a1);
                        q1 = fma2(hA2.y, wB[2 * k4 + 1], q1);
                        a2 = fma2(hB2.x, wA[2 * k4 + 2], a2);
                        q2 = fma2(hB2.x, wB[2 * k4 + 2], q2);
                        a3 = fma2(hB2.y, wA[2 * k4 + 3], a3);
                        q3 = fma2(hB2.y, wB[2 * k4 + 3], q3);
                    }
                    a0 = add2(add2(a0, a1), add2(a2, a3));
                    q0 = add2(add2(q0, q1), add2(q2, q3));
                    float2 sa = upk2(a0);
                    float2 sq = upk2(q0);
                    float pre = sa.x + sa.y + xvB;
                    gbufB[g] = (gtype == 2) ? tanh_fast(pre) : sig_fast(pre);
                    if (tj > 0) xwoB[(size_t)(tj - 1) * G4_] = sq.x + sq.y + b1g;
                }
                __syncthreads();

                if (g < F_) {                       // chain A update
                    float iv = gbufA[g];
                    float fv = gbufA[g + 64];
                    float gg = gbufA[g + 128];
                    float ov = gbufA[g + 192];
                    cA = fv * cA + iv * gg;
                    hA_s[g] = ov * tanh_fast(cA);
                } else if (g < 2 * F_) {            // chain B update
                    int u = g - F_;
                    float iv = gbufB[u];
                    float fv = gbufB[u + 64];
                    float gg = gbufB[u + 128];
                    float ov = gbufB[u + 192];
                    cB = fv * cB + iv * gg;
                    hB_s[u] = ov * tanh_fast(cB);
                }
                __syncthreads();
            }
            if ((t & 4) && g == 0) {
                __threadfence();
                *(volatile int*)&prog[bA] = t + 3;
            }
        }
        // epilogue: publish xw1[S-1] for both chains from final h0[S-1]
        {
            ull q0 = 0, q1 = 0, q2 = 0, q3 = 0;
#pragma unroll
            for (int k4 = 0; k4 < 16; k4 += 2) {
                ulonglong2 hA2 = h4A[k4];
                ulonglong2 hB2 = h4A[k4 + 1];
                q0 = fma2(hA2.x, wB[2 * k4 + 0], q0);
                q1 = fma2(hA2.y, wB[2 * k4 + 1], q1);
                q2 = fma2(hB2.x, wB[2 * k4 + 2], q2);
                q3 = fma2(hB2.y, wB[2 * k4 + 3], q3);
            }
            q0 = add2(add2(q0, q1), add2(q2, q3));
            float2 sq = upk2(q0);
            xwoA[(size_t)(S_ - 1) * G4_] = sq.x + sq.y + b1g;
        }
        {
            ull q0 = 0, q1 = 0, q2 = 0, q3 = 0;
#pragma unroll
            for (int k4 = 0; k4 < 16; k4 += 2) {
                ulonglong2 hA2 = h4B[k4];
                ulonglong2 hB2 = h4B[k4 + 1];
                q0 = fma2(hA2.x, wB[2 * k4 + 0], q0);
                q1 = fma2(hA2.y, wB[2 * k4 + 1], q1);
                q2 = fma2(hB2.x, wB[2 * k4 + 2], q2);
                q3 = fma2(hB2.y, wB[2 * k4 + 3], q3);
            }
            q0 = add2(add2(q0, q1), add2(q2, q3));
            float2 sq = upk2(q0);
            xwoB[(size_t)(S_ - 1) * G4_] = sq.x + sq.y + b1g;
        }
        __syncthreads();
        if (g == 0) {
            __threadfence();
            *(volatile int*)&prog[bA] = S_;
        }
    } else {
        // ---------------- consumer: layer1 recurrence, two chains ----------
        ull w2[32];
#pragma unroll
        for (int k2 = 0; k2 < 32; k2++) {
            w2[k2] = pk2(Wh1[(size_t)(2 * k2) * G4_ + g],
                         Wh1[(size_t)(2 * k2 + 1) * G4_ + g]);
        }

        if (g < F_) { hA_s[g] = 0.0f; hB_s[g] = 0.0f; }
        float cA = 0.0f, cB = 0.0f;

        const float* xwbA = xw1 + (size_t)bA * S_ * G4_ + g;
        const float* xwbB = xw1 + (size_t)bB * S_ * G4_ + g;
        const volatile int* pf = &prog[bA];
        int seen = 0;

        {
            int need = (8 < S_) ? 8 : S_;
            while (seen < need) { seen = *pf; if (seen < need) __nanosleep(64); }
            __threadfence();
        }
        float xwbufA[4], xwbufB[4];
#pragma unroll
        for (int j = 0; j < 4; j++) {
            xwbufA[j] = __ldcg(xwbA + (size_t)j * G4_);
            xwbufB[j] = __ldcg(xwbB + (size_t)j * G4_);
        }
        __syncthreads();

        for (int t = 0; t < S_; t += 4) {
            int need = (t + 8 < S_) ? (t + 8) : S_;
            if (seen < need) {
                while (seen < need) { seen = *pf; if (seen < need) __nanosleep(64); }
                __threadfence();
            }
#pragma unroll
            for (int j = 0; j < 4; j++) {
                const int tn = t + 4 + j;
                float xvA = xwbufA[j], xvB = xwbufB[j];
                if (tn < S_) {
                    xwbufA[j] = __ldcg(xwbA + (size_t)tn * G4_);
                    xwbufB[j] = __ldcg(xwbB + (size_t)tn * G4_);
                }

                {
                    ull a0 = 0, a1 = 0, a2 = 0, a3 = 0;
#pragma unroll
                    for (int k4 = 0; k4 < 16; k4 += 2) {
                        ulonglong2 hA2 = h4A[k4];
                        ulonglong2 hB2 = h4A[k4 + 1];
                        a0 = fma2(hA2.x, w2[2 * k4 + 0], a0);
                        a1 = fma2(hA2.y, w2[2 * k4 + 1], a1);
                        a2 = fma2(hB2.x, w2[2 * k4 + 2], a2);
                        a3 = fma2(hB2.y, w2[2 * k4 + 3], a3);
                    }
                    a0 = add2(add2(a0, a1), add2(a2, a3));
                    float2 sv = upk2(a0);
                    float pre = sv.x + sv.y + xvA;
                    gbufA[g] = (gtype == 2) ? tanh_fast(pre) : sig_fast(pre);
                }
                {
                    ull a0 = 0, a1 = 0, a2 = 0, a3 = 0;
#pragma unroll
                    for (int k4 = 0; k4 < 16; k4 += 2) {
                        ulonglong2 hA2 = h4B[k4];
                        ulonglong2 hB2 = h4B[k4 + 1];
                        a0 = fma2(hA2.x, w2[2 * k4 + 0], a0);
                        a1 = fma2(hA2.y, w2[2 * k4 + 1], a1);
                        a2 = fma2(hB2.x, w2[2 * k4 + 2], a2);
                        a3 = fma2(hB2.y, w2[2 * k4 + 3], a3);
                    }
                    a0 = add2(add2(a0, a1), add2(a2, a3));
                    float2 sv = upk2(a0);
                    float pre = sv.x + sv.y + xvB;
                    gbufB[g] = (gtype == 2) ? tanh_fast(pre) : sig_fast(pre);
                }
                __syncthreads();

                if (g < F_) {
                    float iv = gbufA[g];
                    float fv = gbufA[g + 64];
                    float gg = gbufA[g + 128];
                    float ov = gbufA[g + 192];
                    cA = fv * cA + iv * gg;
                    hA_s[g] = ov * tanh_fast(cA);
                } else if (g < 2 * F_) {
                    int u = g - F_;
                    float iv = gbufB[u];
                    float fv = gbufB[u + 64];
                    float gg = gbufB[u + 128];
                    float ov = gbufB[u + 192];
                    cB = fv * cB + iv * gg;
                    hB_s[u] = ov * tanh_fast(cB);
                }
                __syncthreads();
            }
        }
        if (g < F_) c_final[bA * F_ + g] = cA;
        else if (g < 2 * F_) c_final[bB * F_ + (g - F_)] = cB;
    }
}

// ---------------------------------------------------------------------------
// Tiny dense head
// ---------------------------------------------------------------------------
__global__ void dense_head(const float* __restrict__ cf,
                           const float* __restrict__ wd,
                           const float* __restrict__ bd,
                           float* __restrict__ out) {
    int t = threadIdx.x;
    if (t >= B_ * 10) return;
    int b = t / 10, n = t % 10;
    float s = bd[n];
#pragma unroll
    for (int k = 0; k < F_; k++) s += cf[b * F_ + k] * wd[k * 10 + n];
    out[b * 10 + n] = s;
}

// ---------------------------------------------------------------------------
extern "C" void kernel_launch(void* const* d_in, const int* in_sizes, int n_in,
                              void* d_out, int out_size) {
    const float* x       = (const float*)d_in[0];
    const float* conv_w0 = (const float*)d_in[1];
    const float* conv_b0 = (const float*)d_in[2];
    const float* conv_w1 = (const float*)d_in[3];
    const float* conv_b1 = (const float*)d_in[4];
    const float* conv_w2 = (const float*)d_in[5];
    const float* conv_b2 = (const float*)d_in[6];
    const float* Wx0     = (const float*)d_in[7];
    const float* Wh0     = (const float*)d_in[8];
    const float* b0      = (const float*)d_in[9];
    const float* Wx1     = (const float*)d_in[10];
    const float* Wh1     = (const float*)d_in[11];
    const float* b1      = (const float*)d_in[12];
    const float* dense_w = (const float*)d_in[13];
    const float* dense_b = (const float*)d_in[14];
    float* out = (float*)d_out;

    void *pA, *pB, *pXW0, *pXW1, *pPR, *pCF;
    cudaGetSymbolAddress(&pA, g_bufA);
    cudaGetSymbolAddress(&pB, g_bufB);
    cudaGetSymbolAddress(&pXW0, g_xw0);
    cudaGetSymbolAddress(&pXW1, g_xw1);
    cudaGetSymbolAddress(&pPR, g_prog);
    cudaGetSymbolAddress(&pCF, g_cfinal);
    float* bufA = (float*)pA;
    float* bufB = (float*)pB;
    float* xw0  = (float*)pXW0;
    float* xw1  = (float*)pXW1;
    int*   prog = (int*)pPR;
    float* cfin = (float*)pCF;

    dim3 convGrid(S_ / 64, 1, B_);
    dim3 gemmGrid(S_ / 64, G4_ / 64, B_);

    // CNN stack
    conv_gemm<3, true><<<convGrid, 256>>>(x, conv_w0, conv_b0, bufA, 128, 64);
    conv_gemm<3, true><<<convGrid, 256>>>(bufA, conv_w1, conv_b1, bufB, 64, 64);
    conv_gemm<3, true><<<convGrid, 256>>>(bufB, conv_w2, conv_b2, bufA, 64, 64);

    // LSTM layer0 input projection (big parallel GEMM)
    conv_gemm<1, false><<<gemmGrid, 256>>>(bufA, Wx0, b0, xw0, 64, 256);

    // Pipelined 2-layer recurrence, 2 chains per CTA
    lstm_pipe<<<2 * 32, 256>>>(xw0, Wh0, Wx1, b1, Wh1, xw1, prog, cfin);

    // Dense head
    dense_head<<<1, B_ * 10>>>(cfin, dense_w, dense_b, out);
}

// round 12
// speedup vs baseline: 1.7369x; 1.0924x over previous
#include <cuda_runtime.h>
#include <cstdint>

#define B_    64
#define S_    4096
#define F_    64
#define G4_   256   // 4 * F_
#define RING_ 16

// ---------------- scratch (no cudaMalloc allowed) ----------------
__device__ float g_bufA[(size_t)B_ * S_ * F_];    // conv0 out / conv2 out
__device__ float g_bufB[(size_t)B_ * S_ * F_];    // conv1 out
__device__ float g_xw0[(size_t)B_ * S_ * G4_];    // layer0 gate pre-activations
__device__ float g_cfinal[B_ * F_];

typedef unsigned long long ull;

// ---------------- packed f32x2 helpers (sm_103a FFMA2 path) ----------------
__device__ __forceinline__ ull fma2(ull a, ull b, ull c) {
    ull d;
    asm("fma.rn.f32x2 %0, %1, %2, %3;" : "=l"(d) : "l"(a), "l"(b), "l"(c));
    return d;
}
__device__ __forceinline__ ull add2(ull a, ull b) {
    ull d;
    asm("add.rn.f32x2 %0, %1, %2;" : "=l"(d) : "l"(a), "l"(b));
    return d;
}
__device__ __forceinline__ ull dup2(float a) {
    ull d;
    asm("mov.b64 %0, {%1, %1};" : "=l"(d) : "f"(a));
    return d;
}
__device__ __forceinline__ ull pk2(float lo, float hi) {
    ull d;
    asm("mov.b64 %0, {%1, %2};" : "=l"(d) : "f"(lo), "f"(hi));
    return d;
}
__device__ __forceinline__ float2 upk2(ull v) {
    float2 r;
    asm("mov.b64 {%0, %1}, %2;" : "=f"(r.x), "=f"(r.y) : "l"(v));
    return r;
}

// HW tanh.approx (single MUFU)
__device__ __forceinline__ float tanh_fast(float x) {
    float r;
    asm("tanh.approx.f32 %0, %1;" : "=f"(r) : "f"(x));
    return r;
}
__device__ __forceinline__ float sig_fast(float x) {
    return fmaf(0.5f, tanh_fast(0.5f * x), 0.5f);
}

#define WG_BAR(id) asm volatile("bar.sync %0, 256;" :: "r"(id) : "memory")

// ---------------------------------------------------------------------------
// Fused conv1d / GEMM kernel (unchanged, known-good R2/R6 version).
// ---------------------------------------------------------------------------
template <int KW, bool RELU>
__global__ void __launch_bounds__(256)
conv_gemm(const float* __restrict__ xin, const float* __restrict__ w,
          const float* __restrict__ bias, float* __restrict__ out,
          int Cin, int Cout) {
    constexpr int PAD = KW / 2;
    constexpr int RX = 64 + KW - 1;

    __shared__ __align__(16) float xs[66][16];
    __shared__ __align__(16) float ws[KW][16][64];

    const int tid = threadIdx.x;
    const int tx = tid & 15;
    const int ty = tid >> 4;
    const int s0 = blockIdx.x * 64;
    const int co0 = blockIdx.y * 64;
    const int b = blockIdx.z;

    const float* xb = xin + (size_t)b * S_ * Cin;

    ull a01[4], a23[4];
#pragma unroll
    for (int i = 0; i < 4; i++) { a01[i] = 0ull; a23[i] = 0ull; }

    for (int ck = 0; ck < Cin; ck += 16) {
        __syncthreads();
        for (int idx = tid; idx < RX * 16; idx += 256) {
            int r = idx >> 4, k = idx & 15;
            int sg = s0 + r - PAD;
            float v = 0.0f;
            if (sg >= 0 && sg < S_) v = xb[(size_t)sg * Cin + ck + k];
            xs[r][k] = v;
        }
        for (int idx = tid; idx < KW * 16 * 64; idx += 256) {
            int c = idx & 63, k = (idx >> 6) & 15, dk = idx >> 10;
            ws[dk][k][c] = w[((size_t)dk * Cin + (ck + k)) * Cout + co0 + c];
        }
        __syncthreads();

#pragma unroll
        for (int dk = 0; dk < KW; dk++) {
#pragma unroll
            for (int k = 0; k < 16; k++) {
                ulonglong2 wv =
                    *reinterpret_cast<const ulonglong2*>(&ws[dk][k][tx << 2]);
#pragma unroll
                for (int i = 0; i < 4; i++) {
                    ull av = dup2(xs[ty * 4 + i + dk][k]);
                    a01[i] = fma2(av, wv.x, a01[i]);
                    a23[i] = fma2(av, wv.y, a23[i]);
                }
            }
        }
    }

    const int c0 = co0 + (tx << 2);
    const float bb0 = bias[c0 + 0], bb1 = bias[c0 + 1];
    const float bb2 = bias[c0 + 2], bb3 = bias[c0 + 3];
#pragma unroll
    for (int i = 0; i < 4; i++) {
        float2 v01 = upk2(a01[i]);
        float2 v23 = upk2(a23[i]);
        float4 o;
        o.x = v01.x + bb0; o.y = v01.y + bb1;
        o.z = v23.x + bb2; o.w = v23.y + bb3;
        if (RELU) {
            o.x = fmaxf(o.x, 0.0f); o.y = fmaxf(o.y, 0.0f);
            o.z = fmaxf(o.z, 0.0f); o.w = fmaxf(o.w, 0.0f);
        }
        int sg = s0 + ty * 4 + i;
        *reinterpret_cast<float4*>(&out[((size_t)b * S_ + sg) * Cout + c0]) = o;
    }
}

// ---------------------------------------------------------------------------
// Fused 2-layer LSTM: ONE CTA per batch, 512 threads = 2 warp-groups.
// WG0 (threads 0-255): layer0 recurrence + LOWER half (k=0..31) of the Wx1
//   projection of h0 (fused over the same h_s0 SMEM loads).
// WG1 (threads 256-511): layer1 recurrence + UPPER half (k=32..63) of the
//   Wx1 projection, reading h0 from a 16-slot SMEM ring, 8 steps behind.
// Cross-WG sync: __syncthreads every 4 steps (rendezvous); intra-WG per-step
// gate exchange via named barriers (1 for WG0, 2 for WG1).
// No global flags, fences, or xw1 stream — everything stays in the CTA.
// ---------------------------------------------------------------------------
__global__ void __launch_bounds__(512, 1)
lstm_fused(const float* __restrict__ xw0, const float* __restrict__ Wh0,
           const float* __restrict__ Wx1, const float* __restrict__ b1v,
           const float* __restrict__ Wh1, float* __restrict__ c_final) {
    const int b = blockIdx.x;
    const int tid = threadIdx.x;
    const int wg = tid >> 8;            // 0 or 1
    const int g = tid & 255;            // gate column
    const int gtype = g >> 6;

    __shared__ __align__(16) float h_s0[F_];
    __shared__ __align__(16) float h_s1[F_];
    __shared__ float gbuf0[G4_];
    __shared__ float gbuf1[G4_];
    __shared__ __align__(16) float h0ring[RING_][F_];
    __shared__ __align__(16) float p0ring[RING_][G4_];

    const ulonglong2* h40 = reinterpret_cast<const ulonglong2*>(h_s0);
    const ulonglong2* h41 = reinterpret_cast<const ulonglong2*>(h_s1);

    // weights: main recurrent dot (32 ull) + half of Wx1 (16 ull)
    ull wM[32], wX[16];
    float b1g = 0.0f;
    if (wg == 0) {
#pragma unroll
        for (int k2 = 0; k2 < 32; k2++)
            wM[k2] = pk2(Wh0[(size_t)(2 * k2) * G4_ + g],
                         Wh0[(size_t)(2 * k2 + 1) * G4_ + g]);
#pragma unroll
        for (int k2 = 0; k2 < 16; k2++)          // Wx1 rows 0..31
            wX[k2] = pk2(Wx1[(size_t)(2 * k2) * G4_ + g],
                         Wx1[(size_t)(2 * k2 + 1) * G4_ + g]);
        if (g < F_) { h_s0[g] = 0.0f; }
    } else {
#pragma unroll
        for (int k2 = 0; k2 < 32; k2++)
            wM[k2] = pk2(Wh1[(size_t)(2 * k2) * G4_ + g],
                         Wh1[(size_t)(2 * k2 + 1) * G4_ + g]);
#pragma unroll
        for (int k2 = 0; k2 < 16; k2++)          // Wx1 rows 32..63
            wX[k2] = pk2(Wx1[(size_t)(32 + 2 * k2) * G4_ + g],
                         Wx1[(size_t)(33 + 2 * k2) * G4_ + g]);
        b1g = b1v[g];
        if (g < F_) { h_s1[g] = 0.0f; }
    }
    float c_reg = 0.0f;

    const float* xwb = xw0 + (size_t)b * S_ * G4_ + g;
    float xwbuf[4];
    if (wg == 0) {
#pragma unroll
        for (int j = 0; j < 4; j++) xwbuf[j] = xwb[(size_t)j * G4_];
    }
    __syncthreads();

    const int NGROUP = S_ / 4;               // 1024
    for (int k = 0; k < NGROUP + 2; k++) {
        __syncthreads();                     // group rendezvous

        if (wg == 0) {
            if (k < NGROUP) {
                const int t0 = 4 * k;
#pragma unroll
                for (int j = 0; j < 4; j++) {
                    const int tj = t0 + j;
                    float xv = xwbuf[j];
                    int tn = tj + 4;
                    if (tn < S_) xwbuf[j] = xwb[(size_t)tn * G4_];

                    // fused: Wh0 dot + lower Wx1 partial over SAME h_s0
                    ull a0 = 0, a1 = 0, a2 = 0, a3 = 0;
                    ull q0 = 0, q1 = 0;
#pragma unroll
                    for (int k4 = 0; k4 < 8; k4++) {
                        ulonglong2 hA = h40[k4];          // comps 0..31
                        a0 = fma2(hA.x, wM[2 * k4 + 0], a0);
                        q0 = fma2(hA.x, wX[2 * k4 + 0], q0);
                        a1 = fma2(hA.y, wM[2 * k4 + 1], a1);
                        q1 = fma2(hA.y, wX[2 * k4 + 1], q1);
                    }
#pragma unroll
                    for (int k4 = 8; k4 < 16; k4++) {
                        ulonglong2 hB = h40[k4];          // comps 32..63
                        a2 = fma2(hB.x, wM[2 * k4 + 0], a2);
                        a3 = fma2(hB.y, wM[2 * k4 + 1], a3);
                    }
                    a0 = add2(add2(a0, a1), add2(a2, a3));
                    q0 = add2(q0, q1);
                    float2 sa = upk2(a0);
                    float2 sq = upk2(q0);
                    float pre = sa.x + sa.y + xv;

                    float gv = (gtype == 2) ? tanh_fast(pre) : sig_fast(pre);
                    gbuf0[g] = gv;
                    // lower Wx1 partial of h0[tj-1] (h_s0 held h0[tj-1])
                    if (tj > 0)
                        p0ring[(tj - 1) & (RING_ - 1)][g] = sq.x + sq.y;
                    WG_BAR(1);

                    if (g < F_) {
                        float iv = gbuf0[g];
                        float fv = gbuf0[g + 64];
                        float gg = gbuf0[g + 128];
                        float ov = gbuf0[g + 192];
                        c_reg = fv * c_reg + iv * gg;
                        float hv = ov * tanh_fast(c_reg);
                        h_s0[g] = hv;
                        h0ring[tj & (RING_ - 1)][g] = hv;
                    }
                    WG_BAR(1);
                }
            } else if (k == NGROUP) {
                // publish lower partial for the final h0[S-1]
                ull q0 = 0, q1 = 0;
#pragma unroll
                for (int k4 = 0; k4 < 8; k4++) {
                    ulonglong2 hA = h40[k4];
                    q0 = fma2(hA.x, wX[2 * k4 + 0], q0);
                    q1 = fma2(hA.y, wX[2 * k4 + 1], q1);
                }
                q0 = add2(q0, q1);
                float2 sq = upk2(q0);
                p0ring[(S_ - 1) & (RING_ - 1)][g] = sq.x + sq.y;
            }
        } else {
            if (k >= 2) {
                const int u0 = 4 * (k - 2);
#pragma unroll
                for (int j = 0; j < 4; j++) {
                    const int u = u0 + j;
                    const int slot = u & (RING_ - 1);
                    const ulonglong2* x4 =
                        reinterpret_cast<const ulonglong2*>(h0ring[slot]);

                    ull a0 = 0, a1 = 0, a2 = 0, a3 = 0;
                    ull q0 = 0, q1 = 0;
#pragma unroll
                    for (int k4 = 0; k4 < 8; k4++) {
                        ulonglong2 hA = h41[k4];
                        a0 = fma2(hA.x, wM[2 * k4 + 0], a0);
                        a1 = fma2(hA.y, wM[2 * k4 + 1], a1);
                    }
#pragma unroll
                    for (int k4 = 8; k4 < 16; k4++) {
                        ulonglong2 hB = h41[k4];
                        ulonglong2 xB = x4[k4];           // h0 comps 32..63
                        a2 = fma2(hB.x, wM[2 * k4 + 0], a2);
                        q0 = fma2(xB.x, wX[2 * (k4 - 8) + 0], q0);
                        a3 = fma2(hB.y, wM[2 * k4 + 1], a3);
                        q1 = fma2(xB.y, wX[2 * (k4 - 8) + 1], q1);
                    }
                    a0 = add2(add2(a0, a1), add2(a2, a3));
                    q0 = add2(q0, q1);
                    float2 sa = upk2(a0);
                    float2 sq = upk2(q0);
                    float pre = sa.x + sa.y + sq.x + sq.y +
                                p0ring[slot][g] + b1g;

                    float gv = (gtype == 2) ? tanh_fast(pre) : sig_fast(pre);
                    gbuf1[g] = gv;
                    WG_BAR(2);

                    if (g < F_) {
                        float iv = gbuf1[g];
                        float fv = gbuf1[g + 64];
                        float gg = gbuf1[g + 128];
                        float ov = gbuf1[g + 192];
                        c_reg = fv * c_reg + iv * gg;
                        h_s1[g] = ov * tanh_fast(c_reg);
                    }
                    WG_BAR(2);
                }
            }
        }
    }

    if (wg == 1 && g < F_) c_final[b * F_ + g] = c_reg;
}

// ---------------------------------------------------------------------------
// Tiny dense head
// ---------------------------------------------------------------------------
__global__ void dense_head(const float* __restrict__ cf,
                           const float* __restrict__ wd,
                           const float* __restrict__ bd,
                           float* __restrict__ out) {
    int t = threadIdx.x;
    if (t >= B_ * 10) return;
    int b = t / 10, n = t % 10;
    float s = bd[n];
#pragma unroll
    for (int k = 0; k < F_; k++) s += cf[b * F_ + k] * wd[k * 10 + n];
    out[b * 10 + n] = s;
}

// ---------------------------------------------------------------------------
extern "C" void kernel_launch(void* const* d_in, const int* in_sizes, int n_in,
                              void* d_out, int out_size) {
    const float* x       = (const float*)d_in[0];
    const float* conv_w0 = (const float*)d_in[1];
    const float* conv_b0 = (const float*)d_in[2];
    const float* conv_w1 = (const float*)d_in[3];
    const float* conv_b1 = (const float*)d_in[4];
    const float* conv_w2 = (const float*)d_in[5];
    const float* conv_b2 = (const float*)d_in[6];
    const float* Wx0     = (const float*)d_in[7];
    const float* Wh0     = (const float*)d_in[8];
    const float* b0      = (const float*)d_in[9];
    const float* Wx1     = (const float*)d_in[10];
    const float* Wh1     = (const float*)d_in[11];
    const float* b1      = (const float*)d_in[12];
    const float* dense_w = (const float*)d_in[13];
    const float* dense_b = (const float*)d_in[14];
    float* out = (float*)d_out;

    void *pA, *pB, *pXW0, *pCF;
    cudaGetSymbolAddress(&pA, g_bufA);
    cudaGetSymbolAddress(&pB, g_bufB);
    cudaGetSymbolAddress(&pXW0, g_xw0);
    cudaGetSymbolAddress(&pCF, g_cfinal);
    float* bufA = (float*)pA;
    float* bufB = (float*)pB;
    float* xw0  = (float*)pXW0;
    float* cfin = (float*)pCF;

    dim3 convGrid(S_ / 64, 1, B_);
    dim3 gemmGrid(S_ / 64, G4_ / 64, B_);

    // CNN stack
    conv_gemm<3, true><<<convGrid, 256>>>(x, conv_w0, conv_b0, bufA, 128, 64);
    conv_gemm<3, true><<<convGrid, 256>>>(bufA, conv_w1, conv_b1, bufB, 64, 64);
    conv_gemm<3, true><<<convGrid, 256>>>(bufB, conv_w2, conv_b2, bufA, 64, 64);

    // LSTM layer0 input projection (big parallel GEMM)
    conv_gemm<1, false><<<gemmGrid, 256>>>(bufA, Wx0, b0, xw0, 64, 256);

    // Fused 2-layer recurrence: 1 CTA per batch, 2 warp-groups, SMEM rings
    lstm_fused<<<B_, 512>>>(xw0, Wh0, Wx1, b1, Wh1, cfin);

    // Dense head
    dense_head<<<1, B_ * 10>>>(cfin, dense_w, dense_b, out);
}

// round 13
// speedup vs baseline: 1.9520x; 1.1238x over previous
#include <cuda_runtime.h>
#include <cstdint>

#define B_    64
#define S_    4096
#define F_    64
#define G4_   256   // 4 * F_

// ---------------- scratch (no cudaMalloc allowed) ----------------
__device__ float g_bufA[(size_t)B_ * S_ * F_];    // conv0 out / conv2 out
__device__ float g_bufB[(size_t)B_ * S_ * F_];    // conv1 out
__device__ float g_xw0[(size_t)B_ * S_ * G4_];    // layer0 gate pre-activations
__device__ float g_xw1[(size_t)B_ * S_ * G4_];    // layer1 gate pre-activations
__device__ int   g_prog[B_];                      // producer progress flags
__device__ float g_cfinal[B_ * F_];

typedef unsigned long long ull;

// ---------------- packed f32x2 helpers (sm_103a FFMA2 path) ----------------
__device__ __forceinline__ ull fma2(ull a, ull b, ull c) {
    ull d;
    asm("fma.rn.f32x2 %0, %1, %2, %3;" : "=l"(d) : "l"(a), "l"(b), "l"(c));
    return d;
}
__device__ __forceinline__ ull add2(ull a, ull b) {
    ull d;
    asm("add.rn.f32x2 %0, %1, %2;" : "=l"(d) : "l"(a), "l"(b));
    return d;
}
__device__ __forceinline__ ull dup2(float a) {
    ull d;
    asm("mov.b64 %0, {%1, %1};" : "=l"(d) : "f"(a));
    return d;
}
__device__ __forceinline__ ull pk2(float lo, float hi) {
    ull d;
    asm("mov.b64 %0, {%1, %2};" : "=l"(d) : "f"(lo), "f"(hi));
    return d;
}
__device__ __forceinline__ float2 upk2(ull v) {
    float2 r;
    asm("mov.b64 {%0, %1}, %2;" : "=f"(r.x), "=f"(r.y) : "l"(v));
    return r;
}

// HW tanh.approx (single MUFU)
__device__ __forceinline__ float tanh_fast(float x) {
    float r;
    asm("tanh.approx.f32 %0, %1;" : "=f"(r) : "f"(x));
    return r;
}
__device__ __forceinline__ float sig_fast(float x) {
    return fmaf(0.5f, tanh_fast(0.5f * x), 0.5f);
}

// ---------------------------------------------------------------------------
// Fused conv1d / GEMM kernel — R6 structure, K-tile widened 16 -> 32
// (halves __syncthreads count and staging-loop trips; same FMA count).
// ---------------------------------------------------------------------------
template <int KW, bool RELU>
__global__ void __launch_bounds__(256)
conv_gemm(const float* __restrict__ xin, const float* __restrict__ w,
          const float* __restrict__ bias, float* __restrict__ out,
          int Cin, int Cout) {
    constexpr int PAD = KW / 2;
    constexpr int RX = 64 + KW - 1;
    constexpr int TK = 32;

    __shared__ __align__(16) float xs[66][TK];
    __shared__ __align__(16) float ws[KW][TK][64];

    const int tid = threadIdx.x;
    const int tx = tid & 15;
    const int ty = tid >> 4;
    const int s0 = blockIdx.x * 64;
    const int co0 = blockIdx.y * 64;
    const int b = blockIdx.z;

    const float* xb = xin + (size_t)b * S_ * Cin;

    ull a01[4], a23[4];
#pragma unroll
    for (int i = 0; i < 4; i++) { a01[i] = 0ull; a23[i] = 0ull; }

    for (int ck = 0; ck < Cin; ck += TK) {
        __syncthreads();
        for (int idx = tid; idx < RX * TK; idx += 256) {
            int r = idx >> 5, k = idx & (TK - 1);
            int sg = s0 + r - PAD;
            float v = 0.0f;
            if (sg >= 0 && sg < S_) v = xb[(size_t)sg * Cin + ck + k];
            xs[r][k] = v;
        }
        for (int idx = tid; idx < KW * TK * 64; idx += 256) {
            int c = idx & 63, k = (idx >> 6) & (TK - 1), dk = idx >> 11;
            ws[dk][k][c] = w[((size_t)dk * Cin + (ck + k)) * Cout + co0 + c];
        }
        __syncthreads();

#pragma unroll
        for (int dk = 0; dk < KW; dk++) {
#pragma unroll
            for (int k = 0; k < TK; k++) {
                ulonglong2 wv =
                    *reinterpret_cast<const ulonglong2*>(&ws[dk][k][tx << 2]);
#pragma unroll
                for (int i = 0; i < 4; i++) {
                    ull av = dup2(xs[ty * 4 + i + dk][k]);
                    a01[i] = fma2(av, wv.x, a01[i]);
                    a23[i] = fma2(av, wv.y, a23[i]);
                }
            }
        }
    }

    const int c0 = co0 + (tx << 2);
    const float bb0 = bias[c0 + 0], bb1 = bias[c0 + 1];
    const float bb2 = bias[c0 + 2], bb3 = bias[c0 + 3];
#pragma unroll
    for (int i = 0; i < 4; i++) {
        float2 v01 = upk2(a01[i]);
        float2 v23 = upk2(a23[i]);
        float4 o;
        o.x = v01.x + bb0; o.y = v01.y + bb1;
        o.z = v23.x + bb2; o.w = v23.y + bb3;
        if (RELU) {
            o.x = fmaxf(o.x, 0.0f); o.y = fmaxf(o.y, 0.0f);
            o.z = fmaxf(o.z, 0.0f); o.w = fmaxf(o.w, 0.0f);
        }
        int sg = s0 + ty * 4 + i;
        *reinterpret_cast<float4*>(&out[((size_t)b * S_ + sg) * Cout + c0]) = o;
    }
}

// ---------------------------------------------------------------------------
// Pipelined 2-layer LSTM recurrence — EXACT R6 structure; only change:
// fence/flag epoch widened from 8 to 16 steps (amortizes MEMBAR.GPU and the
// consumer's acquire fence 2x). Consumer lag grows by <=16 steps (~6us tail).
// ---------------------------------------------------------------------------
__global__ void __launch_bounds__(256, 1)
lstm_pipe(const float* __restrict__ xw0, const float* __restrict__ Wh0,
          const float* __restrict__ Wx1, const float* __restrict__ b1v,
          const float* __restrict__ Wh1,
          float* __restrict__ xw1, int* __restrict__ prog,
          float* __restrict__ c_final) {
    const int b = blockIdx.x & 63;
    const bool producer = blockIdx.x < 64;
    const int g = threadIdx.x;
    const int gtype = g >> 6;

    __shared__ __align__(16) float h_s[F_];
    __shared__ float gbuf[G4_];

    const ulonglong2* h4 = reinterpret_cast<const ulonglong2*>(h_s);

    if (producer) {
        ull wA[32], wB[32];
#pragma unroll
        for (int k2 = 0; k2 < 32; k2++) {
            wA[k2] = pk2(Wh0[(size_t)(2 * k2) * G4_ + g],
                         Wh0[(size_t)(2 * k2 + 1) * G4_ + g]);
            wB[k2] = pk2(Wx1[(size_t)(2 * k2) * G4_ + g],
                         Wx1[(size_t)(2 * k2 + 1) * G4_ + g]);
        }
        const float b1g = b1v[g];

        if (g < F_) h_s[g] = 0.0f;
        float c_reg = 0.0f;

        const float* xwb = xw0 + (size_t)b * S_ * G4_ + g;
        float* xwo = xw1 + (size_t)b * S_ * G4_ + g;
        float xwbuf[4];
#pragma unroll
        for (int j = 0; j < 4; j++) xwbuf[j] = xwb[(size_t)j * G4_];
        __syncthreads();

        for (int t = 0; t < S_; t += 4) {
#pragma unroll
            for (int j = 0; j < 4; j++) {
                const int tj = t + j;
                float xv = xwbuf[j];
                int tn = tj + 4;
                if (tn < S_) xwbuf[j] = xwb[(size_t)tn * G4_];

                ull a0 = 0, a1 = 0, a2 = 0, a3 = 0;
                ull q0 = 0, q1 = 0, q2 = 0, q3 = 0;
#pragma unroll
                for (int k4 = 0; k4 < 16; k4 += 2) {
                    ulonglong2 hA = h4[k4];
                    ulonglong2 hB = h4[k4 + 1];
                    a0 = fma2(hA.x, wA[2 * k4 + 0], a0);
                    q0 = fma2(hA.x, wB[2 * k4 + 0], q0);
                    a1 = fma2(hA.y, wA[2 * k4 + 1], a1);
                    q1 = fma2(hA.y, wB[2 * k4 + 1], q1);
                    a2 = fma2(hB.x, wA[2 * k4 + 2], a2);
                    q2 = fma2(hB.x, wB[2 * k4 + 2], q2);
                    a3 = fma2(hB.y, wA[2 * k4 + 3], a3);
                    q3 = fma2(hB.y, wB[2 * k4 + 3], q3);
                }
                a0 = add2(add2(a0, a1), add2(a2, a3));
                q0 = add2(add2(q0, q1), add2(q2, q3));
                float2 sa = upk2(a0);
                float2 sq = upk2(q0);
                float pre = sa.x + sa.y + xv;

                float gv = (gtype == 2) ? tanh_fast(pre) : sig_fast(pre);
                gbuf[g] = gv;
                if (tj > 0) xwo[(size_t)(tj - 1) * G4_] = sq.x + sq.y + b1g;
                __syncthreads();

                if (g < F_) {
                    float iv = gbuf[g];
                    float fv = gbuf[g + 64];
                    float gg = gbuf[g + 128];
                    float ov = gbuf[g + 192];
                    c_reg = fv * c_reg + iv * gg;
                    h_s[g] = ov * tanh_fast(c_reg);
                }
                __syncthreads();
            }
            // epoch-16 release: at t = 12, 28, 44, ... entries 0..t+2 valid
            if ((t & 12) == 12 && g == 0) {
                __threadfence();
                *(volatile int*)&prog[b] = t + 3;
            }
        }
        // epilogue: publish xw1[S-1] using final h0[S-1]
        {
            ull q0 = 0, q1 = 0, q2 = 0, q3 = 0;
#pragma unroll
            for (int k4 = 0; k4 < 16; k4 += 2) {
                ulonglong2 hA = h4[k4];
                ulonglong2 hB = h4[k4 + 1];
                q0 = fma2(hA.x, wB[2 * k4 + 0], q0);
                q1 = fma2(hA.y, wB[2 * k4 + 1], q1);
                q2 = fma2(hB.x, wB[2 * k4 + 2], q2);
                q3 = fma2(hB.y, wB[2 * k4 + 3], q3);
            }
            q0 = add2(add2(q0, q1), add2(q2, q3));
            float2 sq = upk2(q0);
            xwo[(size_t)(S_ - 1) * G4_] = sq.x + sq.y + b1g;
        }
        __syncthreads();
        if (g == 0) {
            __threadfence();
            *(volatile int*)&prog[b] = S_;
        }
    } else {
        // ---------------- consumer: layer1 recurrence ----------------
        ull w2[32];
#pragma unroll
        for (int k2 = 0; k2 < 32; k2++) {
            w2[k2] = pk2(Wh1[(size_t)(2 * k2) * G4_ + g],
                         Wh1[(size_t)(2 * k2 + 1) * G4_ + g]);
        }

        if (g < F_) h_s[g] = 0.0f;
        float c_reg = 0.0f;

        const float* xwb = xw1 + (size_t)b * S_ * G4_ + g;
        const volatile int* pf = &prog[b];
        int seen = 0;

        {
            int need = (8 < S_) ? 8 : S_;
            while (seen < need) { seen = *pf; if (seen < need) __nanosleep(64); }
            __threadfence();
        }
        float xwbuf[4];
#pragma unroll
        for (int j = 0; j < 4; j++) xwbuf[j] = __ldcg(xwb + (size_t)j * G4_);
        __syncthreads();

        for (int t = 0; t < S_; t += 4) {
            int need = (t + 8 < S_) ? (t + 8) : S_;
            if (seen < need) {
                while (seen < need) { seen = *pf; if (seen < need) __nanosleep(64); }
                __threadfence();
            }
#pragma unroll
            for (int j = 0; j < 4; j++) {
                float xv = xwbuf[j];
                int tn = t + 4 + j;
                if (tn < S_) xwbuf[j] = __ldcg(xwb + (size_t)tn * G4_);

                ull a0 = 0, a1 = 0, a2 = 0, a3 = 0;
#pragma unroll
                for (int k4 = 0; k4 < 16; k4 += 2) {
                    ulonglong2 hA = h4[k4];
                    ulonglong2 hB = h4[k4 + 1];
                    a0 = fma2(hA.x, w2[2 * k4 + 0], a0);
                    a1 = fma2(hA.y, w2[2 * k4 + 1], a1);
                    a2 = fma2(hB.x, w2[2 * k4 + 2], a2);
                    a3 = fma2(hB.y, w2[2 * k4 + 3], a3);
                }
                a0 = add2(add2(a0, a1), add2(a2, a3));
                float2 sv = upk2(a0);
                float pre = sv.x + sv.y + xv;

                float gv = (gtype == 2) ? tanh_fast(pre) : sig_fast(pre);
                gbuf[g] = gv;
                __syncthreads();

                if (g < F_) {
                    float iv = gbuf[g];
                    float fv = gbuf[g + 64];
                    float gg = gbuf[g + 128];
                    float ov = gbuf[g + 192];
                    c_reg = fv * c_reg + iv * gg;
                    h_s[g] = ov * tanh_fast(c_reg);
                }
                __syncthreads();
            }
        }
        if (g < F_) c_final[b * F_ + g] = c_reg;
    }
}

// ---------------------------------------------------------------------------
// Tiny dense head
// ---------------------------------------------------------------------------
__global__ void dense_head(const float* __restrict__ cf,
                           const float* __restrict__ wd,
                           const float* __restrict__ bd,
                           float* __restrict__ out) {
    int t = threadIdx.x;
    if (t >= B_ * 10) return;
    int b = t / 10, n = t % 10;
    float s = bd[n];
#pragma unroll
    for (int k = 0; k < F_; k++) s += cf[b * F_ + k] * wd[k * 10 + n];
    out[b * 10 + n] = s;
}

// ---------------------------------------------------------------------------
extern "C" void kernel_launch(void* const* d_in, const int* in_sizes, int n_in,
                              void* d_out, int out_size) {
    const float* x       = (const float*)d_in[0];
    const float* conv_w0 = (const float*)d_in[1];
    const float* conv_b0 = (const float*)d_in[2];
    const float* conv_w1 = (const float*)d_in[3];
    const float* conv_b1 = (const float*)d_in[4];
    const float* conv_w2 = (const float*)d_in[5];
    const float* conv_b2 = (const float*)d_in[6];
    const float* Wx0     = (const float*)d_in[7];
    const float* Wh0     = (const float*)d_in[8];
    const float* b0      = (const float*)d_in[9];
    const float* Wx1     = (const float*)d_in[10];
    const float* Wh1     = (const float*)d_in[11];
    const float* b1      = (const float*)d_in[12];
    const float* dense_w = (const float*)d_in[13];
    const float* dense_b = (const float*)d_in[14];
    float* out = (float*)d_out;

    void *pA, *pB, *pXW0, *pXW1, *pPR, *pCF;
    cudaGetSymbolAddress(&pA, g_bufA);
    cudaGetSymbolAddress(&pB, g_bufB);
    cudaGetSymbolAddress(&pXW0, g_xw0);
    cudaGetSymbolAddress(&pXW1, g_xw1);
    cudaGetSymbolAddress(&pPR, g_prog);
    cudaGetSymbolAddress(&pCF, g_cfinal);
    float* bufA = (float*)pA;
    float* bufB = (float*)pB;
    float* xw0  = (float*)pXW0;
    float* xw1  = (float*)pXW1;
    int*   prog = (int*)pPR;
    float* cfin = (float*)pCF;

    dim3 convGrid(S_ / 64, 1, B_);
    dim3 gemmGrid(S_ / 64, G4_ / 64, B_);

    // CNN stack
    conv_gemm<3, true><<<convGrid, 256>>>(x, conv_w0, conv_b0, bufA, 128, 64);
    conv_gemm<3, true><<<convGrid, 256>>>(bufA, conv_w1, conv_b1, bufB, 64, 64);
    conv_gemm<3, true><<<convGrid, 256>>>(bufB, conv_w2, conv_b2, bufA, 64, 64);

    // LSTM layer0 input projection (big parallel GEMM)
    conv_gemm<1, false><<<gemmGrid, 256>>>(bufA, Wx0, b0, xw0, 64, 256);

    // Pipelined 2-layer recurrence (layer1 xw computed by producers on the fly)
    lstm_pipe<<<2 * B_, 256>>>(xw0, Wh0, Wx1, b1, Wh1, xw1, prog, cfin);

    // Dense head
    dense_head<<<1, B_ * 10>>>(cfin, dense_w, dense_b, out);
}